// round 2
// baseline (speedup 1.0000x reference)
#include <cuda_runtime.h>
#include <cstring>

// GRU encoder: B=64, T=24, N=184, HID=128, input dim 2.
// SEQ = B*N = 11776 independent recurrent sequences.
// Each warp owns TM=5 sequences; full T-loop runs in-kernel with only
// __syncwarp (h state is warp-private in shared). W_hh staged once per block
// into 192KB of shared as float4 k-quads. Inner GEMM uses packed fma.rn.f32x2
// (2 fp32 FMAs per issue slot) -> ~2x fp32 throughput on sm_103a.

#define BB 64
#define TT 24
#define NN 184
#define HID 128
#define SEQ (BB*NN)            // 11776
#define TM 5                   // seqs per warp
#define NWARPS 8
#define NTHREADS (NWARPS*32)
#define GRID 148
#define NTASKS ((SEQ + TM - 1)/TM)   // 2356
#define TASK_STRIDE (GRID*NWARPS)    // 1184
#define H_ELEMS ((size_t)BB*TT*NN*HID)  // 36175872

// shared layout (floats)
#define SH_WQ      0            // 12288 float4 = 49152 floats (Wq[k4][j])
#define SH_BIH     49152        // 384
#define SH_BHH     (SH_BIH+384)
#define SH_W0      (SH_BHH+384)
#define SH_W1      (SH_W0+384)
#define SH_FCW     (SH_W1+384)  // 128
#define SH_H       (SH_FCW+128) // 8 warps * 5 * 128 = 5120
#define SH_FLOATS  (SH_H + NWARPS*TM*HID)
#define SMEM_BYTES (SH_FLOATS*4)   // 223744 bytes

__device__ __forceinline__ void fma2(unsigned long long& d,
                                     unsigned long long a,
                                     unsigned long long b) {
    asm("fma.rn.f32x2 %0, %1, %2, %0;" : "+l"(d) : "l"(a), "l"(b));
}

__device__ __forceinline__ float lohi(unsigned long long v) {
    return __uint_as_float((unsigned)v) + __uint_as_float((unsigned)(v >> 32));
}

__global__ void __launch_bounds__(NTHREADS, 1)
gru_encoder_kernel(const float* __restrict__ pm,     // [B,T,N,1]
                   const float* __restrict__ Wih,    // [384,2]
                   const float* __restrict__ Whh,    // [384,128]
                   const float* __restrict__ bih_g,  // [384]
                   const float* __restrict__ bhh_g,  // [384]
                   const float* __restrict__ fcw_g,  // [1,128]
                   const float* __restrict__ fcb_g,  // [1]
                   float* __restrict__ out)          // H then xn_final
{
    extern __shared__ float smem[];
    const int tid  = threadIdx.x;
    const int lane = tid & 31;
    const int w    = tid >> 5;

    // ---- stage W_hh into shared as k-quad-major float4: Wq[k4*384 + j] = W[j][4k4..4k4+3]
    float4* Wq = reinterpret_cast<float4*>(smem + SH_WQ);
    {
        const float4* Wg = reinterpret_cast<const float4*>(Whh);
        for (int idx = tid; idx < 384*32; idx += NTHREADS) {
            int k4 = idx & 31, j = idx >> 5;
            Wq[k4*384 + j] = Wg[j*32 + k4];
        }
    }
    float* bih = smem + SH_BIH;
    float* bhh = smem + SH_BHH;
    float* w0s = smem + SH_W0;
    float* w1s = smem + SH_W1;
    float* fcw = smem + SH_FCW;
    for (int i = tid; i < 384; i += NTHREADS) {
        bih[i] = bih_g[i];
        bhh[i] = bhh_g[i];
        w0s[i] = Wih[2*i + 0];   // multiplies x_prev
        w1s[i] = Wih[2*i + 1];   // multiplies pm_t
    }
    if (tid < HID) fcw[tid] = fcw_g[tid];
    __syncthreads();

    const float fcb = fcb_g[0];
    float* hw = smem + SH_H + w*(TM*HID);   // warp-private h state [TM][128]

    float fw[4];
#pragma unroll
    for (int u = 0; u < 4; u++) fw[u] = fcw[lane + 32*u];

    int joff[12];
#pragma unroll
    for (int jj = 0; jj < 12; jj++)
        joff[jj] = (jj >> 2)*128 + (jj & 3)*32 + lane;

    const unsigned long long* WqU_base =
        reinterpret_cast<const unsigned long long*>(Wq);

    const int wg = blockIdx.x * NWARPS + w;

    for (int task = wg; task < NTASKS; task += TASK_STRIDE) {
        const int s0 = task * TM;

        // init warp-private state
#pragma unroll
        for (int m = 0; m < TM; m++)
#pragma unroll
            for (int u = 0; u < 4; u++)
                hw[m*HID + lane + 32*u] = 0.f;

        float xp[TM];
        int   cs[TM];
        bool  valid[TM];
#pragma unroll
        for (int m = 0; m < TM; m++) {
            int s = s0 + m;
            valid[m] = (s < SEQ);
            int ss = valid[m] ? s : 0;
            int b = ss / NN, n = ss % NN;
            cs[m] = b*TT*NN + n;       // pm idx = cs + t*N ; H idx = (cs + t*N)*HID
            xp[m] = 0.f;
        }

        for (int t = 0; t < TT; t++) {
            __syncwarp();  // prior-step h writes (other lanes) -> this-step GEMM reads

            // ---------- GEMM: acc2[jj][m] (f32x2 partial sums over even/odd k)
            unsigned long long acc[12][TM];
#pragma unroll
            for (int jj = 0; jj < 12; jj++)
#pragma unroll
                for (int m = 0; m < TM; m++) acc[jj][m] = 0ULL;

#pragma unroll 2
            for (int k4 = 0; k4 < 32; k4++) {
                unsigned long long h4x[TM], h4y[TM];
#pragma unroll
                for (int m = 0; m < TM; m++) {
                    ulonglong2 hv = reinterpret_cast<const ulonglong2*>(hw + m*HID)[k4];
                    h4x[m] = hv.x; h4y[m] = hv.y;
                }
                const unsigned long long* Wrow = WqU_base + (size_t)k4*768;
#pragma unroll
                for (int jj = 0; jj < 12; jj++) {
                    unsigned long long wx = Wrow[2*joff[jj] + 0];
                    unsigned long long wy = Wrow[2*joff[jj] + 1];
#pragma unroll
                    for (int m = 0; m < TM; m++) {
                        fma2(acc[jj][m], h4x[m], wx);
                        fma2(acc[jj][m], h4y[m], wy);
                    }
                }
            }

            // ---------- gates + state update + H store
            float pmv[TM];
#pragma unroll
            for (int m = 0; m < TM; m++)
                pmv[m] = valid[m] ? pm[cs[m] + t*NN] : 0.f;

            float px[TM];
#pragma unroll
            for (int m = 0; m < TM; m++) px[m] = 0.f;

#pragma unroll
            for (int u = 0; u < 4; u++) {
                const int hi = lane + 32*u;
                const float bir = bih[hi], biz = bih[128+hi], bin = bih[256+hi];
                const float bhr = bhh[hi], bhz = bhh[128+hi], bhn = bhh[256+hi];
                const float w0r = w0s[hi], w0z = w0s[128+hi], w0n = w0s[256+hi];
                const float w1r = w1s[hi], w1z = w1s[128+hi], w1n = w1s[256+hi];
#pragma unroll
                for (int m = 0; m < TM; m++) {
                    const float x = xp[m], p = pmv[m];
                    const float gr = lohi(acc[0+u][m]) + bhr + (w0r*x + w1r*p + bir);
                    const float gz = lohi(acc[4+u][m]) + bhz + (w0z*x + w1z*p + biz);
                    const float r  = 1.f / (1.f + __expf(-gr));
                    const float z  = 1.f / (1.f + __expf(-gz));
                    const float a  = (w0n*x + w1n*p + bin)
                                   + r * (lohi(acc[8+u][m]) + bhn);
                    // overflow-safe tanh
                    const float e  = __expf(-2.f * fabsf(a));
                    const float nt = copysignf((1.f - e) / (1.f + e), a);
                    const float ho = hw[m*HID + hi];
                    const float hn = nt + z * (ho - nt);   // (1-z)*nt + z*ho
                    hw[m*HID + hi] = hn;
                    if (valid[m])
                        out[(size_t)(cs[m] + t*NN) * HID + hi] = hn;
                    px[m] += hn * fw[u];
                }
            }

            // fc: x_{t} = h_new . fc_w + fc_b   (butterfly -> all lanes hold sum)
#pragma unroll
            for (int m = 0; m < TM; m++) {
                float v = px[m];
#pragma unroll
                for (int o = 16; o; o >>= 1)
                    v += __shfl_xor_sync(0xFFFFFFFFu, v, o);
                xp[m] = v + fcb;
                if (t == TT-1 && valid[m] && lane == 0)
                    out[H_ELEMS + (size_t)(s0 + m)] = xp[m];
            }
        }
    }
}

extern "C" void kernel_launch(void* const* d_in, const int* in_sizes, int n_in,
                              void* d_out, int out_size) {
    (void)in_sizes; (void)n_in; (void)out_size;
    const float* pm  = (const float*)d_in[0];
    const float* Wih = (const float*)d_in[1];
    const float* Whh = (const float*)d_in[2];
    const float* bih = (const float*)d_in[3];
    const float* bhh = (const float*)d_in[4];
    const float* fcw = (const float*)d_in[5];
    const float* fcb = (const float*)d_in[6];
    float* out = (float*)d_out;

    cudaFuncSetAttribute(gru_encoder_kernel,
                         cudaFuncAttributeMaxDynamicSharedMemorySize,
                         SMEM_BYTES);
    gru_encoder_kernel<<<GRID, NTHREADS, SMEM_BYTES>>>(
        pm, Wih, Whh, bih, bhh, fcw, fcb, out);
}

// round 4
// speedup vs baseline: 1.7416x; 1.7416x over previous
#include <cuda_runtime.h>
#include <cuda_bf16.h>
#include <cstdint>

// GRU encoder via mma.sync (HMMA bf16, baseline PTX — no tcgen05).
// gh = h @ W_hh^T in 3 bf16 passes (Ahi*Whi + Ahi*Wlo + Alo*Whi).
// Whi + A(hi/lo) in smem; Wlo pre-packed in fragment order in a device global.

#define TT 24
#define NNN 184
#define SEQ 11776
#define M_CTA 80
#define GRIDX 148
#define NT 256
#define H_ELEMS 36175872ULL

// smem byte offsets
#define SM_WHI    0
#define SM_AHI    98304
#define SM_ALO    118784
#define SM_W0     139264
#define SM_W1     140800
#define SM_BS     142336   /* bsr[128], bsz[128], bin[128], bhn[128] */
#define SM_FCW    144384
#define SM_PMROW  144896
#define SM_XROW   145216
#define SM_CSROW  145536
#define SM_XPART  145856
#define SMEM_BYTES 148416

__device__ __align__(16) uint32_t g_wlofrag[8 * 32 * 96];

__device__ __forceinline__ uint32_t smem_u32(const void* p) {
    uint32_t a;
    asm("{ .reg .u64 t; cvta.to.shared.u64 t, %1; cvt.u32.u64 %0, t; }" : "=r"(a) : "l"(p));
    return a;
}

#define LDSM4(r0, r1, r2, r3, addr) \
    asm volatile("ldmatrix.sync.aligned.m8n8.x4.shared.b16 {%0,%1,%2,%3}, [%4];" \
        : "=r"(r0), "=r"(r1), "=r"(r2), "=r"(r3) : "r"(addr))

#define MMA16816(c, a, b) \
    asm volatile("mma.sync.aligned.m16n8k16.row.col.f32.bf16.bf16.f32 " \
        "{%0,%1,%2,%3}, {%4,%5,%6,%7}, {%8,%9}, {%0,%1,%2,%3};" \
        : "+f"((c)[0]), "+f"((c)[1]), "+f"((c)[2]), "+f"((c)[3]) \
        : "r"((a)[0]), "r"((a)[1]), "r"((a)[2]), "r"((a)[3]), \
          "r"((b)[0]), "r"((b)[1]))

__device__ __forceinline__ uint32_t packbf2(float x, float y) {
    return (uint32_t)__bfloat16_as_ushort(__float2bfloat16(x))
         | ((uint32_t)__bfloat16_as_ushort(__float2bfloat16(y)) << 16);
}
__device__ __forceinline__ float sigf(float x) {
    return __fdividef(1.f, 1.f + __expf(-x));
}
__device__ __forceinline__ float tanhfast(float a) {
    return 1.f - 2.f * __fdividef(1.f, 1.f + __expf(2.f * a));
}

// ---- setup: pack Wlo = W - bf16(W) into per-thread fragment order ----
__global__ void pack_wlo_kernel(const float* __restrict__ Whh) {
    int t = blockIdx.x * blockDim.x + threadIdx.x;
    if (t >= 8 * 32 * 96) return;
    int r = t & 1, i = (t >> 1) % 6, K = (t / 12) & 7, l = (t / 96) & 31, w = t / 3072;
    int tile = w + 8 * (i & 1) + 16 * (i >> 1);
    int j = 8 * tile + (l >> 2);
    int k0 = 16 * K + 8 * r + 2 * (l & 3);
    float w0 = Whh[j * 128 + k0], w1 = Whh[j * 128 + k0 + 1];
    float l0 = w0 - __bfloat162float(__float2bfloat16(w0));
    float l1 = w1 - __bfloat162float(__float2bfloat16(w1));
    g_wlofrag[t] = packbf2(l0, l1);
}

__global__ void __launch_bounds__(NT, 1)
gru_mma_kernel(const float* __restrict__ pm,
               const float* __restrict__ Wih,
               const float* __restrict__ Whh,
               const float* __restrict__ bih_g,
               const float* __restrict__ bhh_g,
               const float* __restrict__ fcw_g,
               const float* __restrict__ fcb_g,
               float* __restrict__ out)
{
    extern __shared__ char smem[];
    const uint32_t smb = smem_u32(smem);
    const int tid = threadIdx.x;
    const int lane = tid & 31;
    const int w = tid >> 5;
    const int bid80 = blockIdx.x * M_CTA;

    float* w0s   = (float*)(smem + SM_W0);
    float* w1s   = (float*)(smem + SM_W1);
    float* bss   = (float*)(smem + SM_BS);
    float* fcws  = (float*)(smem + SM_FCW);
    float* pmrow = (float*)(smem + SM_PMROW);
    float* xrow  = (float*)(smem + SM_XROW);
    int*   csrow = (int*)  (smem + SM_CSROW);
    float* xpart = (float*)(smem + SM_XPART);

    // stage Whi (bf16, swizzled) : addr = j*256 + (((k>>3)^(j&7))<<4) + (k&7)*2
    {
        const float4* Wg = (const float4*)Whh;
        for (int v = tid; v < 384 * 32; v += NT) {
            int j = v >> 5, k4 = (v & 31) * 4;
            float4 wv = Wg[v];
            uint32_t off = (uint32_t)(j * 256 + ((((k4 >> 3) ^ (j & 7))) << 4) + (k4 & 7) * 2);
            uint2 pk = make_uint2(packbf2(wv.x, wv.y), packbf2(wv.z, wv.w));
            *(uint2*)(smem + SM_WHI + off) = pk;
        }
    }
    // zero A hi+lo (contiguous 40960 B)
    for (int v = tid; v < 40960 / 8; v += NT)
        ((uint2*)(smem + SM_AHI))[v] = make_uint2(0u, 0u);

    for (int i = tid; i < 384; i += NT) { w0s[i] = Wih[2 * i]; w1s[i] = Wih[2 * i + 1]; }
    if (tid < 128) {
        bss[tid]       = bih_g[tid]       + bhh_g[tid];         // r
        bss[128 + tid] = bih_g[128 + tid] + bhh_g[128 + tid];   // z
        bss[256 + tid] = bih_g[256 + tid];                       // i_n bias
        bss[384 + tid] = bhh_g[256 + tid];                       // h_n bias
        fcws[tid] = fcw_g[tid];
    }
    if (tid < M_CTA) {
        int s = bid80 + tid;
        bool v = s < SEQ;
        int ss = v ? s : 0;
        int b = ss / NNN, n = ss % NNN;
        csrow[tid] = b * TT * NNN + n;
        pmrow[tid] = v ? pm[b * TT * NNN + n] : 0.f;
        xrow[tid] = 0.f;
    }
    __syncthreads();

    // per-thread ldmatrix lane roles
    const int rA  = (lane & 7) + ((lane >> 3) & 1) * 8;  // A row-in-tile
    const int cA  = lane >> 4;                           // A k-16B sel
    const int cBh = (lane >> 3) & 1;                     // B k-16B sel
    const int jW0 = 8 * w + 64 * (lane >> 4) + (lane & 7);
    const int q   = lane >> 2, p4 = lane & 3;
    const int lx7 = lane & 7;

    uint32_t aRow[5], wRow[3];
#pragma unroll
    for (int mt = 0; mt < 5; mt++) aRow[mt] = (uint32_t)((16 * mt + rA) * 256);
#pragma unroll
    for (int pp = 0; pp < 3; pp++) wRow[pp] = (uint32_t)((jW0 + 128 * pp) * 256);

    const uint4* wloP = (const uint4*)g_wlofrag + (w * 32 + lane) * 24;
    const float fcb = fcb_g[0];

    float hold[40];
#pragma unroll
    for (int i = 0; i < 40; i++) hold[i] = 0.f;

    for (int t = 0; t < TT; t++) {
        float acc[6][5][4];
#pragma unroll
        for (int i = 0; i < 6; i++)
#pragma unroll
            for (int mt = 0; mt < 5; mt++)
#pragma unroll
                for (int e = 0; e < 4; e++) acc[i][mt][e] = 0.f;

        // pass 1+2: Ahi x Whi  +  Ahi x Wlo
#pragma unroll
        for (int K = 0; K < 8; K++) {
            const uint32_t offA = (uint32_t)(((2 * K + cA) ^ lx7) << 4);
            uint32_t a[5][4];
#pragma unroll
            for (int mt = 0; mt < 5; mt++)
                LDSM4(a[mt][0], a[mt][1], a[mt][2], a[mt][3],
                      smb + SM_AHI + aRow[mt] + offA);
            const uint32_t offW = (uint32_t)(((2 * K + cBh) ^ lx7) << 4);
            uint32_t bh[6][2];
#pragma unroll
            for (int pp = 0; pp < 3; pp++) {
                uint32_t r0, r1, r2, r3;
                LDSM4(r0, r1, r2, r3, smb + SM_WHI + wRow[pp] + offW);
                bh[2 * pp][0] = r0; bh[2 * pp][1] = r1;
                bh[2 * pp + 1][0] = r2; bh[2 * pp + 1][1] = r3;
            }
            uint32_t bl[6][2];
#pragma unroll
            for (int c = 0; c < 3; c++) {
                uint4 v = __ldg(wloP + K * 3 + c);
                bl[2 * c][0] = v.x; bl[2 * c][1] = v.y;
                bl[2 * c + 1][0] = v.z; bl[2 * c + 1][1] = v.w;
            }
#pragma unroll
            for (int i = 0; i < 6; i++)
#pragma unroll
                for (int mt = 0; mt < 5; mt++) {
                    MMA16816(acc[i][mt], a[mt], bh[i]);
                    MMA16816(acc[i][mt], a[mt], bl[i]);
                }
        }
        // pass 3: Alo x Whi
#pragma unroll
        for (int K = 0; K < 8; K++) {
            const uint32_t offA = (uint32_t)(((2 * K + cA) ^ lx7) << 4);
            uint32_t a[5][4];
#pragma unroll
            for (int mt = 0; mt < 5; mt++)
                LDSM4(a[mt][0], a[mt][1], a[mt][2], a[mt][3],
                      smb + SM_ALO + aRow[mt] + offA);
            const uint32_t offW = (uint32_t)(((2 * K + cBh) ^ lx7) << 4);
            uint32_t bh[6][2];
#pragma unroll
            for (int pp = 0; pp < 3; pp++) {
                uint32_t r0, r1, r2, r3;
                LDSM4(r0, r1, r2, r3, smb + SM_WHI + wRow[pp] + offW);
                bh[2 * pp][0] = r0; bh[2 * pp][1] = r1;
                bh[2 * pp + 1][0] = r2; bh[2 * pp + 1][1] = r3;
            }
#pragma unroll
            for (int i = 0; i < 6; i++)
#pragma unroll
                for (int mt = 0; mt < 5; mt++)
                    MMA16816(acc[i][mt], a[mt], bh[i]);
        }
        __syncthreads();   // all A reads done before epilogue overwrites A

        // ---- epilogue: gates, state update, stores ----
        float px[10];
#pragma unroll
        for (int i = 0; i < 10; i++) px[i] = 0.f;

#pragma unroll
        for (int G = 0; G < 2; G++) {
            const int c0 = G * 64 + 8 * w + 2 * p4;
            float w0r[2], w1r[2], br[2], w0z[2], w1z[2], bz[2],
                  w0n[2], w1n[2], bi_n[2], bh_n[2], fc[2];
#pragma unroll
            for (int e = 0; e < 2; e++) {
                const int c = c0 + e;
                w0r[e] = w0s[c];       w1r[e] = w1s[c];       br[e]  = bss[c];
                w0z[e] = w0s[128 + c]; w1z[e] = w1s[128 + c]; bz[e]  = bss[128 + c];
                w0n[e] = w0s[256 + c]; w1n[e] = w1s[256 + c];
                bi_n[e] = bss[256 + c]; bh_n[e] = bss[384 + c];
                fc[e] = fcws[c];
            }
#pragma unroll
            for (int mt = 0; mt < 5; mt++)
#pragma unroll
                for (int hf = 0; hf < 2; hf++) {
                    const int row = 16 * mt + 8 * hf + q;
                    const float xm = xrow[row], pv = pmrow[row];
                    float hn2[2];
#pragma unroll
                    for (int e = 0; e < 2; e++) {
                        const int ridx = hf * 2 + e;
                        const float gr = acc[G][mt][ridx]
                            + fmaf(w0r[e], xm, fmaf(w1r[e], pv, br[e]));
                        const float gz = acc[2 + G][mt][ridx]
                            + fmaf(w0z[e], xm, fmaf(w1z[e], pv, bz[e]));
                        const float r = sigf(gr);
                        const float z = sigf(gz);
                        const float an = fmaf(w0n[e], xm, fmaf(w1n[e], pv, bi_n[e]))
                            + r * (acc[4 + G][mt][ridx] + bh_n[e]);
                        const float ntv = tanhfast(an);
                        const int hi_ = mt * 8 + G * 4 + hf * 2 + e;
                        const float ho = hold[hi_];
                        const float hn = ntv + z * (ho - ntv);
                        hold[hi_] = hn;
                        px[mt * 2 + hf] = fmaf(hn, fc[e], px[mt * 2 + hf]);
                        hn2[e] = hn;
                    }
                    if (bid80 + row < SEQ) {
                        const int cs = csrow[row];
                        *(float2*)(out + (size_t)(cs + t * NNN) * 128 + c0)
                            = make_float2(hn2[0], hn2[1]);
                    }
                    // write h_new back to A smem as bf16 hi/lo (swizzled)
                    float h0 = hn2[0], h1 = hn2[1];
                    float hh0 = __bfloat162float(__float2bfloat16(h0));
                    float hh1 = __bfloat162float(__float2bfloat16(h1));
                    const uint32_t aoff = (uint32_t)(row * 256
                        + (((8 * G + w) ^ q) << 4) + 4 * p4);
                    *(uint32_t*)(smem + SM_AHI + aoff) = packbf2(h0, h1);
                    *(uint32_t*)(smem + SM_ALO + aoff) = packbf2(h0 - hh0, h1 - hh1);
                }
        }

        // fc reduction: sum over 4 lanes (p4), then over 8 warps via smem
#pragma unroll
        for (int rr = 0; rr < 10; rr++) {
            float v = px[rr];
            v += __shfl_xor_sync(0xFFFFFFFFu, v, 1);
            v += __shfl_xor_sync(0xFFFFFFFFu, v, 2);
            if (p4 == 0)
                xpart[w * 80 + 16 * (rr >> 1) + 8 * (rr & 1) + q] = v;
        }
        __syncthreads();
        if (tid < M_CTA) {
            float sx = fcb;
#pragma unroll
            for (int ww = 0; ww < 8; ww++) sx += xpart[ww * 80 + tid];
            xrow[tid] = sx;
            const int s = bid80 + tid;
            const bool v = s < SEQ;
            if (t + 1 < TT) pmrow[tid] = v ? pm[csrow[tid] + (t + 1) * NNN] : 0.f;
            if (t == TT - 1 && v) out[H_ELEMS + (size_t)s] = sx;
        }
        __syncthreads();
    }
}

extern "C" void kernel_launch(void* const* d_in, const int* in_sizes, int n_in,
                              void* d_out, int out_size) {
    (void)in_sizes; (void)n_in; (void)out_size;
    const float* pm  = (const float*)d_in[0];
    const float* Wih = (const float*)d_in[1];
    const float* Whh = (const float*)d_in[2];
    const float* bih = (const float*)d_in[3];
    const float* bhh = (const float*)d_in[4];
    const float* fcw = (const float*)d_in[5];
    const float* fcb = (const float*)d_in[6];
    float* out = (float*)d_out;

    pack_wlo_kernel<<<96, 256>>>(Whh);
    cudaFuncSetAttribute(gru_mma_kernel,
                         cudaFuncAttributeMaxDynamicSharedMemorySize,
                         SMEM_BYTES);
    gru_mma_kernel<<<GRIDX, NT, SMEM_BYTES>>>(
        pm, Wih, Whh, bih, bhh, fcw, fcb, out);
}

// round 5
// speedup vs baseline: 2.5642x; 1.4723x over previous
#include <cuda_runtime.h>
#include <cuda_bf16.h>
#include <cstdint>

// GRU encoder via mma.sync (HMMA bf16). 16 warps/CTA, 148 CTAs x 80 seqs.
// gh = h @ W_hh^T in 3 bf16 passes (Ahi*Whi + Ahi*Wlo + Alo*Whi).
// Warp w owns gate tiles {w, w+16, w+32} (cols 8w..8w+7 of each gate).
// Exact fp32 h state lives in smem (stride 132, conflict-free).

#define TT 24
#define NNN 184
#define SEQ 11776
#define M_CTA 80
#define GRIDX 148
#define NT 512
#define H_ELEMS 36175872ULL
#define HSTRIDE 132

// smem byte offsets
#define SM_WHI    0
#define SM_AHI    98304
#define SM_ALO    118784
#define SM_HST    139264            /* 80*132*4 = 42240 */
#define SM_W0     181504
#define SM_W1     183040
#define SM_BS     184576            /* br[128], bz[128], bin[128], bhn[128] */
#define SM_FCW    186624
#define SM_PMROW  187136
#define SM_XROW   187456
#define SM_CSROW  187776
#define SM_XPART  188096            /* 16*80*4 = 5120 */
#define SMEM_BYTES 193216

__device__ __align__(16) uint32_t g_wlofrag[16 * 32 * 8 * 8];  // 128KB

__device__ __forceinline__ uint32_t smem_u32(const void* p) {
    uint32_t a;
    asm("{ .reg .u64 t; cvta.to.shared.u64 t, %1; cvt.u32.u64 %0, t; }" : "=r"(a) : "l"(p));
    return a;
}

#define LDSM4(r0, r1, r2, r3, addr) \
    asm volatile("ldmatrix.sync.aligned.m8n8.x4.shared.b16 {%0,%1,%2,%3}, [%4];" \
        : "=r"(r0), "=r"(r1), "=r"(r2), "=r"(r3) : "r"(addr))
#define LDSM2(r0, r1, addr) \
    asm volatile("ldmatrix.sync.aligned.m8n8.x2.shared.b16 {%0,%1}, [%2];" \
        : "=r"(r0), "=r"(r1) : "r"(addr))

#define MMA16816(c, a, b) \
    asm volatile("mma.sync.aligned.m16n8k16.row.col.f32.bf16.bf16.f32 " \
        "{%0,%1,%2,%3}, {%4,%5,%6,%7}, {%8,%9}, {%0,%1,%2,%3};" \
        : "+f"((c)[0]), "+f"((c)[1]), "+f"((c)[2]), "+f"((c)[3]) \
        : "r"((a)[0]), "r"((a)[1]), "r"((a)[2]), "r"((a)[3]), \
          "r"((b)[0]), "r"((b)[1]))

__device__ __forceinline__ uint32_t packbf2(float x, float y) {
    return (uint32_t)__bfloat16_as_ushort(__float2bfloat16(x))
         | ((uint32_t)__bfloat16_as_ushort(__float2bfloat16(y)) << 16);
}
__device__ __forceinline__ float sigf(float x) {
    return __fdividef(1.f, 1.f + __expf(-x));
}
__device__ __forceinline__ float tanhfast(float a) {
    return 1.f - 2.f * __fdividef(1.f, 1.f + __expf(2.f * a));
}

// ---- setup: pack Wlo = W - bf16(W) into per-thread fragment order ----
// thread tid in [0, 4096): K = tid&7, l = (tid>>3)&31, w = tid>>8.
// words [tile s, reg r] at g[tid*8 + 2s + r], tiles {w, w+16, w+32}.
__global__ void pack_wlo_kernel(const float* __restrict__ Whh) {
    int t = blockIdx.x * blockDim.x + threadIdx.x;
    if (t >= 4096) return;
    int K = t & 7, l = (t >> 3) & 31, w = t >> 8;
#pragma unroll
    for (int s = 0; s < 3; s++) {
#pragma unroll
        for (int r = 0; r < 2; r++) {
            int tau = w + 16 * s;
            int j = 8 * tau + (l >> 2);
            int k0 = 16 * K + 8 * r + 2 * (l & 3);
            float w0 = Whh[j * 128 + k0], w1 = Whh[j * 128 + k0 + 1];
            float l0 = w0 - __bfloat162float(__float2bfloat16(w0));
            float l1 = w1 - __bfloat162float(__float2bfloat16(w1));
            g_wlofrag[t * 8 + 2 * s + r] = packbf2(l0, l1);
        }
    }
    g_wlofrag[t * 8 + 6] = 0u;
    g_wlofrag[t * 8 + 7] = 0u;
}

__global__ void __launch_bounds__(NT, 1)
gru_mma_kernel(const float* __restrict__ pm,
               const float* __restrict__ Wih,
               const float* __restrict__ Whh,
               const float* __restrict__ bih_g,
               const float* __restrict__ bhh_g,
               const float* __restrict__ fcw_g,
               const float* __restrict__ fcb_g,
               float* __restrict__ out)
{
    extern __shared__ char smem[];
    const uint32_t smb = smem_u32(smem);
    const int tid = threadIdx.x;
    const int lane = tid & 31;
    const int w = tid >> 5;
    const int bid80 = blockIdx.x * M_CTA;

    float* w0s   = (float*)(smem + SM_W0);
    float* w1s   = (float*)(smem + SM_W1);
    float* bss   = (float*)(smem + SM_BS);
    float* fcws  = (float*)(smem + SM_FCW);
    float* pmrow = (float*)(smem + SM_PMROW);
    float* xrow  = (float*)(smem + SM_XROW);
    int*   csrow = (int*)  (smem + SM_CSROW);
    float* xpart = (float*)(smem + SM_XPART);
    float* hst   = (float*)(smem + SM_HST);

    // stage Whi (bf16, swizzled): addr = j*256 + (((k>>3)^(j&7))<<4) + (k&7)*2
    {
        const float4* Wg = (const float4*)Whh;
        for (int v = tid; v < 384 * 32; v += NT) {
            int j = v >> 5, k4 = (v & 31) * 4;
            float4 wv = Wg[v];
            uint32_t off = (uint32_t)(j * 256 + ((((k4 >> 3) ^ (j & 7))) << 4) + (k4 & 7) * 2);
            *(uint2*)(smem + SM_WHI + off) =
                make_uint2(packbf2(wv.x, wv.y), packbf2(wv.z, wv.w));
        }
    }
    // zero A hi+lo (contiguous 40960B) and Hst (42240B)
    for (int v = tid; v < 40960 / 8; v += NT)
        ((uint2*)(smem + SM_AHI))[v] = make_uint2(0u, 0u);
    for (int v = tid; v < 80 * HSTRIDE; v += NT)
        hst[v] = 0.f;

    for (int i = tid; i < 384; i += NT) { w0s[i] = Wih[2 * i]; w1s[i] = Wih[2 * i + 1]; }
    if (tid < 128) {
        bss[tid]       = bih_g[tid]       + bhh_g[tid];         // r
        bss[128 + tid] = bih_g[128 + tid] + bhh_g[128 + tid];   // z
        bss[256 + tid] = bih_g[256 + tid];                       // i_n bias
        bss[384 + tid] = bhh_g[256 + tid];                       // h_n bias
        fcws[tid] = fcw_g[tid];
    }
    if (tid < M_CTA) {
        int s = bid80 + tid;
        bool v = s < SEQ;
        int ss = v ? s : 0;
        int b = ss / NNN, n = ss % NNN;
        csrow[tid] = b * TT * NNN + n;
        pmrow[tid] = v ? pm[b * TT * NNN + n] : 0.f;
        xrow[tid] = 0.f;
    }
    __syncthreads();

    // lane roles
    const int lx7 = lane & 7;
    const int rA  = (lane & 7) + ((lane >> 3) & 1) * 8;   // A row-in-tile
    const int cA  = lane >> 4;                            // A k-16B sel
    const int cB  = (lane >> 3) & 1;                      // W k-16B sel
    const int q   = lane >> 2, p4 = lane & 3;

    // W row base addresses
    const uint32_t wA4 = smb + SM_WHI
        + (uint32_t)((8 * w + (lane & 7) + (((lane >> 4) & 1) << 7)) * 256); // tiles w, w+16
    const uint32_t wA2 = smb + SM_WHI
        + (uint32_t)((8 * w + 256 + (lane & 7)) * 256);                      // tile w+32
    uint32_t aAddr[5];
#pragma unroll
    for (int mt = 0; mt < 5; mt++)
        aAddr[mt] = smb + (uint32_t)((16 * mt + rA) * 256);

    const uint4* wloP = (const uint4*)(g_wlofrag) + (size_t)((w * 32 + lane) * 8) * 2;
    const float fcb = fcb_g[0];
    const int c0 = 8 * w + 2 * p4;

    for (int t = 0; t < TT; t++) {
        float acc[3][5][4];
#pragma unroll
        for (int g = 0; g < 3; g++)
#pragma unroll
            for (int mt = 0; mt < 5; mt++)
#pragma unroll
                for (int e = 0; e < 4; e++) acc[g][mt][e] = 0.f;

        // pass 1+2: Ahi x Whi  +  Ahi x Wlo
#pragma unroll
        for (int K = 0; K < 8; K++) {
            const uint32_t offA = (uint32_t)(((2 * K + cA) ^ lx7) << 4);
            uint32_t a[5][4];
#pragma unroll
            for (int mt = 0; mt < 5; mt++)
                LDSM4(a[mt][0], a[mt][1], a[mt][2], a[mt][3],
                      aAddr[mt] + SM_AHI + offA);
            const uint32_t offW = (uint32_t)(((2 * K + cB) ^ lx7) << 4);
            uint32_t bh[3][2];
            LDSM4(bh[0][0], bh[0][1], bh[1][0], bh[1][1], wA4 + offW);
            LDSM2(bh[2][0], bh[2][1], wA2 + offW);
            uint32_t bl[3][2];
            {
                uint4 v1 = __ldg(wloP + K * 2);
                uint2 v2 = __ldg((const uint2*)(wloP + K * 2 + 1));
                bl[0][0] = v1.x; bl[0][1] = v1.y;
                bl[1][0] = v1.z; bl[1][1] = v1.w;
                bl[2][0] = v2.x; bl[2][1] = v2.y;
            }
#pragma unroll
            for (int g = 0; g < 3; g++)
#pragma unroll
                for (int mt = 0; mt < 5; mt++) {
                    MMA16816(acc[g][mt], a[mt], bh[g]);
                    MMA16816(acc[g][mt], a[mt], bl[g]);
                }
        }
        // pass 3: Alo x Whi
#pragma unroll
        for (int K = 0; K < 8; K++) {
            const uint32_t offA = (uint32_t)(((2 * K + cA) ^ lx7) << 4);
            uint32_t a[5][4];
#pragma unroll
            for (int mt = 0; mt < 5; mt++)
                LDSM4(a[mt][0], a[mt][1], a[mt][2], a[mt][3],
                      aAddr[mt] + SM_ALO + offA);
            const uint32_t offW = (uint32_t)(((2 * K + cB) ^ lx7) << 4);
            uint32_t bh[3][2];
            LDSM4(bh[0][0], bh[0][1], bh[1][0], bh[1][1], wA4 + offW);
            LDSM2(bh[2][0], bh[2][1], wA2 + offW);
#pragma unroll
            for (int g = 0; g < 3; g++)
#pragma unroll
                for (int mt = 0; mt < 5; mt++)
                    MMA16816(acc[g][mt], a[mt], bh[g]);
        }
        __syncthreads();   // all A reads done before epilogue overwrites A

        // ---- epilogue: gates, state update, stores ----
        float w0r[2], w1r[2], br[2], w0z[2], w1z[2], bz[2],
              w0n[2], w1n[2], bi_n[2], bh_n[2], fc[2];
#pragma unroll
        for (int e = 0; e < 2; e++) {
            const int c = c0 + e;
            w0r[e] = w0s[c];       w1r[e] = w1s[c];       br[e] = bss[c];
            w0z[e] = w0s[128 + c]; w1z[e] = w1s[128 + c]; bz[e] = bss[128 + c];
            w0n[e] = w0s[256 + c]; w1n[e] = w1s[256 + c];
            bi_n[e] = bss[256 + c]; bh_n[e] = bss[384 + c];
            fc[e] = fcws[c];
        }

        float px[10];
#pragma unroll
        for (int i = 0; i < 10; i++) px[i] = 0.f;

#pragma unroll
        for (int mt = 0; mt < 5; mt++)
#pragma unroll
            for (int hf = 0; hf < 2; hf++) {
                const int row = 16 * mt + 8 * hf + q;
                const float xm = xrow[row], pv = pmrow[row];
                float2 ho2 = *(float2*)(hst + row * HSTRIDE + c0);
                float hn2[2];
#pragma unroll
                for (int e = 0; e < 2; e++) {
                    const int ridx = hf * 2 + e;
                    const float gr = acc[0][mt][ridx]
                        + fmaf(w0r[e], xm, fmaf(w1r[e], pv, br[e]));
                    const float gz = acc[1][mt][ridx]
                        + fmaf(w0z[e], xm, fmaf(w1z[e], pv, bz[e]));
                    const float r = sigf(gr);
                    const float z = sigf(gz);
                    const float an = fmaf(w0n[e], xm, fmaf(w1n[e], pv, bi_n[e]))
                        + r * (acc[2][mt][ridx] + bh_n[e]);
                    const float ntv = tanhfast(an);
                    const float ho = e ? ho2.y : ho2.x;
                    const float hn = ntv + z * (ho - ntv);
                    px[mt * 2 + hf] = fmaf(hn, fc[e], px[mt * 2 + hf]);
                    hn2[e] = hn;
                }
                *(float2*)(hst + row * HSTRIDE + c0) = make_float2(hn2[0], hn2[1]);
                if (bid80 + row < SEQ)
                    *(float2*)(out + (size_t)(csrow[row] + t * NNN) * 128 + c0)
                        = make_float2(hn2[0], hn2[1]);
                // write h_new back to A smem as bf16 hi/lo (swizzled)
                const float hh0 = __bfloat162float(__float2bfloat16(hn2[0]));
                const float hh1 = __bfloat162float(__float2bfloat16(hn2[1]));
                const uint32_t aoff = (uint32_t)(row * 256 + ((w ^ q) << 4) + 4 * p4);
                *(uint32_t*)(smem + SM_AHI + aoff) = packbf2(hn2[0], hn2[1]);
                *(uint32_t*)(smem + SM_ALO + aoff) = packbf2(hn2[0] - hh0, hn2[1] - hh1);
            }

        // fc reduction: sum over p4, then over 16 warps via smem
#pragma unroll
        for (int rr = 0; rr < 10; rr++) {
            float v = px[rr];
            v += __shfl_xor_sync(0xFFFFFFFFu, v, 1);
            v += __shfl_xor_sync(0xFFFFFFFFu, v, 2);
            if (p4 == 0)
                xpart[w * 80 + 16 * (rr >> 1) + 8 * (rr & 1) + q] = v;
        }
        __syncthreads();
        if (tid < M_CTA) {
            float sx = fcb;
#pragma unroll
            for (int ww = 0; ww < 16; ww++) sx += xpart[ww * 80 + tid];
            xrow[tid] = sx;
            const int s = bid80 + tid;
            const bool v = s < SEQ;
            if (t + 1 < TT) pmrow[tid] = v ? pm[csrow[tid] + (t + 1) * NNN] : 0.f;
            if (t == TT - 1 && v) out[H_ELEMS + (size_t)s] = sx;
        }
        __syncthreads();
    }
}

extern "C" void kernel_launch(void* const* d_in, const int* in_sizes, int n_in,
                              void* d_out, int out_size) {
    (void)in_sizes; (void)n_in; (void)out_size;
    const float* pm  = (const float*)d_in[0];
    const float* Wih = (const float*)d_in[1];
    const float* Whh = (const float*)d_in[2];
    const float* bih = (const float*)d_in[3];
    const float* bhh = (const float*)d_in[4];
    const float* fcw = (const float*)d_in[5];
    const float* fcb = (const float*)d_in[6];
    float* out = (float*)d_out;

    pack_wlo_kernel<<<16, 256>>>(Whh);
    cudaFuncSetAttribute(gru_mma_kernel,
                         cudaFuncAttributeMaxDynamicSharedMemorySize,
                         SMEM_BYTES);
    gru_mma_kernel<<<GRIDX, NT, SMEM_BYTES>>>(
        pm, Wih, Whh, bih, bhh, fcw, fcb, out);
}